// round 3
// baseline (speedup 1.0000x reference)
#include <cuda_runtime.h>

#define T_ 1024
#define B_ 128
#define L_ 128

typedef unsigned long long ull;

// scratch (no allocations allowed)
__device__ float g_den[B_];
__device__ float g_num[B_];

__device__ __forceinline__ ull ffma2(ull a, ull b, ull c) {
    ull d;
    asm("fma.rn.f32x2 %0, %1, %2, %3;" : "=l"(d) : "l"(a), "l"(b), "l"(c));
    return d;
}
__device__ __forceinline__ ull pack2(float lo, float hi) {
    ull d;
    asm("mov.b64 %0, {%1, %2};" : "=l"(d) : "f"(lo), "f"(hi));
    return d;
}
__device__ __forceinline__ float2 unpack2(ull v) {
    float2 f;
    asm("mov.b64 {%0, %1}, %2;" : "=f"(f.x), "=f"(f.y) : "l"(v));
    return f;
}

// padded index for the u vector: 16B pad per 32 floats so the four 32-float
// slices start in disjoint bank groups (slice s base word = 36*s).
#define UPAD(i) ((i) + (((i) >> 5) << 2))
#define U_WORDS (L_ + 16)

// ---------------------------------------------------------------------------
// Denominator. One block (512 thr) per batch b.
// thread (j = tid>>2, s = tid&3): partial dot over i in [32s, 32s+32).
// In-warp layout: lane = (j_local<<2)|s -> slice partials combined by 2 shfl.
// u[j] = exp(score[j] - logZ); renormalize by block max every 4 steps.
// ---------------------------------------------------------------------------
__global__ __launch_bounds__(512) void crf_den_kernel(
    const float* __restrict__ pred,    // (T,B,L)
    const int*   __restrict__ mask,    // (T,B)
    const float* __restrict__ trans,   // (L,L)
    const float* __restrict__ start,   // (L)
    const float* __restrict__ endv)    // (L)
{
    const int b    = blockIdx.x;
    const int tid  = threadIdx.x;
    const int lane = tid & 31;
    const int w    = tid >> 5;
    const int j    = tid >> 2;    // state (column) 0..127
    const int s    = tid & 3;     // slice 0..3
    const int ibase = s << 5;     // 32*s

    // exp(transitions) rows [32s,32s+32) of column j, packed pairs (32 regs)
    ull rT2[16];
#pragma unroll
    for (int k = 0; k < 16; ++k) {
        const int i = ibase + 2 * k;
        rT2[k] = pack2(expf(trans[i * L_ + j]),
                       expf(trans[(i + 1) * L_ + j]));
    }

    __shared__ __align__(16) float e_sh[2][U_WORDS];
    __shared__ float red[16];

    float u    = __expf(start[j] + pred[b * L_ + j]);  // t = 0 (same across s)
    float logZ = 0.0f;
    int   buf  = 0;
    if (s == 0) e_sh[0][UPAD(j)] = u;
    __syncthreads();

    // software-pipelined loads one step ahead
    float p  = pred[(size_t)(B_ * L_) + b * L_ + j];
    int   mk = mask[B_ + b];

    for (int t = 1; t < T_; ++t) {
        float p_next  = 0.0f;
        int   mk_next = 0;
        if (t + 1 < T_) {
            p_next  = pred[(size_t)(t + 1) * (B_ * L_) + b * L_ + j];
            mk_next = mask[(t + 1) * B_ + b];
        }

        // partial = sum_{i in slice} u_prev[i] * expT[i][j]
        const float4* ev =
            reinterpret_cast<const float4*>(&e_sh[buf][36 * s]);
        ull c0 = 0ull, c1 = 0ull, c2 = 0ull, c3 = 0ull;
#pragma unroll
        for (int k = 0; k < 4; ++k) {
            float4 x = ev[2 * k];
            float4 y = ev[2 * k + 1];
            c0 = ffma2(pack2(x.x, x.y), rT2[4 * k + 0], c0);
            c1 = ffma2(pack2(x.z, x.w), rT2[4 * k + 1], c1);
            c2 = ffma2(pack2(y.x, y.y), rT2[4 * k + 2], c2);
            c3 = ffma2(pack2(y.z, y.w), rT2[4 * k + 3], c3);
        }
        float2 f0 = unpack2(c0), f1 = unpack2(c1);
        float2 f2 = unpack2(c2), f3 = unpack2(c3);
        float part = ((f0.x + f0.y) + (f1.x + f1.y)) +
                     ((f2.x + f2.y) + (f3.x + f3.y));

        // combine the 4 slice partials (s lanes are xor-adjacent)
        part += __shfl_xor_sync(0xffffffffu, part, 1);
        part += __shfl_xor_sync(0xffffffffu, part, 2);

        float u_new = part * __expf(p);
        u = mk ? u_new : u;

        // renormalize every 4 steps (block max) to keep fp32 in range
        if ((t & 3) == 0) {
            float m = u;
#pragma unroll
            for (int off = 16; off; off >>= 1)
                m = fmaxf(m, __shfl_xor_sync(0xffffffffu, m, off));
            if (lane == 0) red[w] = m;
            __syncthreads();
            m = red[0];
#pragma unroll
            for (int q = 1; q < 16; ++q) m = fmaxf(m, red[q]);
            logZ += __logf(m);
            u *= (1.0f / m);
        }

        buf ^= 1;
        if (s == 0) e_sh[buf][UPAD(j)] = u;
        __syncthreads();

        p  = p_next;
        mk = mk_next;
    }

    // den[b] = logZ + log( sum_j u[j] * exp(end[j]) )
    float v = (s == 0) ? u * __expf(endv[j]) : 0.0f;
#pragma unroll
    for (int off = 16; off; off >>= 1)
        v += __shfl_xor_sync(0xffffffffu, v, off);
    if (lane == 0) red[w] = v;
    __syncthreads();
    if (tid == 0) {
        float sum = 0.0f;
#pragma unroll
        for (int q = 0; q < 16; ++q) sum += red[q];
        g_den[b] = logZ + __logf(sum);
    }
}

// ---------------------------------------------------------------------------
// Numerator: path score. One block per batch b, 256 threads stride over t.
// Targets may be int64 or int32 (JAX x64 off) — sniff at runtime.
// ---------------------------------------------------------------------------
__global__ __launch_bounds__(256) void crf_num_kernel(
    const float* __restrict__ pred,
    const void*  __restrict__ tgt_raw,
    const int*   __restrict__ mask,
    const float* __restrict__ trans,
    const float* __restrict__ start,
    const float* __restrict__ endv)
{
    const int b    = blockIdx.x;
    const int tid  = threadIdx.x;
    const int lane = tid & 31;
    const int wid  = tid >> 5;

    __shared__ int s_is64;
    if (tid == 0) {
        const unsigned int* wp = (const unsigned int*)tgt_raw;
        int is64 = 1;
#pragma unroll
        for (int k = 0; k < 32; ++k)
            if (wp[2 * k + 1] != 0u) { is64 = 0; break; }
        s_is64 = is64;
    }
    __syncthreads();
    const int is64 = s_is64;
    const long long* t64 = (const long long*)tgt_raw;
    const int*       t32 = (const int*)tgt_raw;

    float local = 0.0f;
    int   mcnt  = 0;

    for (int t = tid; t < T_; t += 256) {
        const int mk = mask[t * B_ + b];
        mcnt += mk;
        if (t >= 1 && mk) {
            const int cur = is64 ? (int)t64[t * B_ + b]       : t32[t * B_ + b];
            const int prv = is64 ? (int)t64[(t - 1) * B_ + b] : t32[(t - 1) * B_ + b];
            local += trans[prv * L_ + cur] +
                     pred[(size_t)t * (B_ * L_) + b * L_ + cur];
        }
    }

    __shared__ float sf[8];
    __shared__ int   si[8];
#pragma unroll
    for (int off = 16; off; off >>= 1) {
        local += __shfl_xor_sync(0xffffffffu, local, off);
        mcnt  += __shfl_xor_sync(0xffffffffu, mcnt,  off);
    }
    if (lane == 0) { sf[wid] = local; si[wid] = mcnt; }
    __syncthreads();

    if (tid == 0) {
        float tot = 0.0f;
        int   mt  = 0;
#pragma unroll
        for (int q = 0; q < 8; ++q) { tot += sf[q]; mt += si[q]; }
        const int t0 = is64 ? (int)t64[b] : t32[b];
        float sc = start[t0] + pred[b * L_ + t0] + tot;
        const int last = mt - 1;
        const int tl = is64 ? (int)t64[last * B_ + b] : t32[last * B_ + b];
        sc += endv[tl];
        g_num[b] = sc;
    }
}

// ---------------------------------------------------------------------------
// Final: out = mean(den - num)
// ---------------------------------------------------------------------------
__global__ __launch_bounds__(B_) void crf_final_kernel(float* __restrict__ out)
{
    const int j    = threadIdx.x;
    const int lane = j & 31;
    const int wid  = j >> 5;

    float v = g_den[j] - g_num[j];
    __shared__ float red[4];
#pragma unroll
    for (int off = 16; off; off >>= 1)
        v += __shfl_xor_sync(0xffffffffu, v, off);
    if (lane == 0) red[wid] = v;
    __syncthreads();
    if (j == 0)
        out[0] = ((red[0] + red[1]) + (red[2] + red[3])) * (1.0f / (float)B_);
}

extern "C" void kernel_launch(void* const* d_in, const int* in_sizes, int n_in,
                              void* d_out, int out_size)
{
    const float* pred  = (const float*)d_in[0];
    const void*  tgt   = (const void*)d_in[1];
    const int*   mask  = (const int*)d_in[2];
    const float* trans = (const float*)d_in[3];
    const float* start = (const float*)d_in[4];
    const float* endv  = (const float*)d_in[5];
    float* out = (float*)d_out;

    crf_den_kernel<<<B_, 512>>>(pred, mask, trans, start, endv);
    crf_num_kernel<<<B_, 256>>>(pred, tgt, mask, trans, start, endv);
    crf_final_kernel<<<1, B_>>>(out);
}

// round 4
// speedup vs baseline: 1.5452x; 1.5452x over previous
#include <cuda_runtime.h>

#define T_ 1024
#define B_ 128
#define L_ 128

typedef unsigned long long ull;

// scratch (no allocations allowed)
__device__ float g_den[B_];
__device__ float g_num[B_];

__device__ __forceinline__ ull ffma2(ull a, ull b, ull c) {
    ull d;
    asm("fma.rn.f32x2 %0, %1, %2, %3;" : "=l"(d) : "l"(a), "l"(b), "l"(c));
    return d;
}
__device__ __forceinline__ ull add2(ull a, ull b) {
    ull d;
    asm("add.rn.f32x2 %0, %1, %2;" : "=l"(d) : "l"(a), "l"(b));
    return d;
}
__device__ __forceinline__ ull pack2(float lo, float hi) {
    ull d;
    asm("mov.b64 %0, {%1, %2};" : "=l"(d) : "f"(lo), "f"(hi));
    return d;
}
__device__ __forceinline__ float2 unpack2(ull v) {
    float2 f;
    asm("mov.b64 {%0, %1}, %2;" : "=f"(f.x), "=f"(f.y) : "l"(v));
    return f;
}

// u vector layout: 16B pad at the 64-float boundary so slice s=1 (base word 68)
// hits banks 4..7 while s=0 (base word 0) hits banks 0..3 -> single LDS phase.
#define UPAD(i) ((i) + (((i) >> 6) << 2))
#define U_WORDS 136

// ---------------------------------------------------------------------------
// Denominator. One block (256 thr, 8 warps) per batch b.
// thread t: j = t>>1 (state/column), s = t&1 (i-slice: [64s, 64s+64)).
// Slice partners are adjacent lanes -> combined with one shfl_xor(1).
// u[j] tracks exp(score[j] - logZ); every 4 steps rescale by broadcast u[0]
// (any consistent positive scale is exact; no block reduction needed).
// ---------------------------------------------------------------------------
__global__ __launch_bounds__(256) void crf_den_kernel(
    const float* __restrict__ pred,    // (T,B,L)
    const int*   __restrict__ mask,    // (T,B)
    const float* __restrict__ trans,   // (L,L)
    const float* __restrict__ start,   // (L)
    const float* __restrict__ endv)    // (L)
{
    const int b    = blockIdx.x;
    const int tid  = threadIdx.x;
    const int lane = tid & 31;
    const int w    = tid >> 5;
    const int j    = tid >> 1;   // 0..127
    const int s    = tid & 1;    // 0..1
    const int ib   = s << 6;     // 64*s

    // exp(transitions) rows [64s, 64s+64) of column j, packed pairs (32 ull)
    ull rT2[32];
#pragma unroll
    for (int k = 0; k < 32; ++k) {
        const int i = ib + 2 * k;
        rT2[k] = pack2(expf(trans[i * L_ + j]),
                       expf(trans[(i + 1) * L_ + j]));
    }

    __shared__ __align__(16) float e_sh[2][U_WORDS];
    __shared__ int   m_sh[T_];
    __shared__ float red[8];

    // preload mask column b (one-time)
    for (int t = tid; t < T_; t += 256)
        m_sh[t] = mask[t * B_ + b];

    float u    = __expf(start[j] + pred[b * L_ + j]);  // t = 0
    float logZ = 0.0f;
    int   buf  = 0;
    if (s == 0) e_sh[0][UPAD(j)] = u;
    __syncthreads();

    // depth-2 prediction prefetch (DRAM latency > 1 step)
    float p0 = pred[(size_t)1 * (B_ * L_) + b * L_ + j];
    float p1 = pred[(size_t)2 * (B_ * L_) + b * L_ + j];

    for (int t = 1; t < T_; ++t) {
        float p2 = 0.0f;
        if (t + 2 < T_)
            p2 = pred[(size_t)(t + 2) * (B_ * L_) + b * L_ + j];
        const int mk = m_sh[t];

        // rescale every 4 steps by broadcast u_prev[0] (in e_sh[buf])
        float inv_m = 1.0f;
        if ((t & 3) == 1 && t > 1) {
            const float m = e_sh[buf][0];   // UPAD(0) == 0
            logZ += __logf(m);
            inv_m = 1.0f / m;
        }

        // partial = sum_{i in slice} u_prev[i] * expT[i][j]
        const ulonglong2* ev =
            reinterpret_cast<const ulonglong2*>(&e_sh[buf][68 * s]);
        ull c0 = 0ull, c1 = 0ull, c2 = 0ull, c3 = 0ull;
#pragma unroll
        for (int k = 0; k < 8; ++k) {
            ulonglong2 x = ev[2 * k];
            ulonglong2 y = ev[2 * k + 1];
            c0 = ffma2(x.x, rT2[4 * k + 0], c0);
            c1 = ffma2(x.y, rT2[4 * k + 1], c1);
            c2 = ffma2(y.x, rT2[4 * k + 2], c2);
            c3 = ffma2(y.y, rT2[4 * k + 3], c3);
        }
        c0 = add2(c0, c1);
        c2 = add2(c2, c3);
        c0 = add2(c0, c2);
        float2 f = unpack2(c0);
        float part = f.x + f.y;

        // combine the two slice partials (partner is lane^1)
        part += __shfl_xor_sync(0xffffffffu, part, 1);

        const float u_new = part * __expf(p0);
        u = (mk ? u_new : u) * inv_m;

        buf ^= 1;
        if (s == 0) e_sh[buf][UPAD(j)] = u;
        __syncthreads();

        p0 = p1;
        p1 = p2;
    }

    // den[b] = logZ + log( sum_j u[j] * exp(end[j]) )
    float v = (s == 0) ? u * __expf(endv[j]) : 0.0f;
#pragma unroll
    for (int off = 16; off; off >>= 1)
        v += __shfl_xor_sync(0xffffffffu, v, off);
    if (lane == 0) red[w] = v;
    __syncthreads();
    if (tid == 0) {
        float sum = 0.0f;
#pragma unroll
        for (int q = 0; q < 8; ++q) sum += red[q];
        g_den[b] = logZ + __logf(sum);
    }
}

// ---------------------------------------------------------------------------
// Numerator: path score. One block per batch b, 256 threads stride over t.
// Targets may be int64 or int32 (JAX x64 off) — sniff at runtime.
// ---------------------------------------------------------------------------
__global__ __launch_bounds__(256) void crf_num_kernel(
    const float* __restrict__ pred,
    const void*  __restrict__ tgt_raw,
    const int*   __restrict__ mask,
    const float* __restrict__ trans,
    const float* __restrict__ start,
    const float* __restrict__ endv)
{
    const int b    = blockIdx.x;
    const int tid  = threadIdx.x;
    const int lane = tid & 31;
    const int wid  = tid >> 5;

    __shared__ int s_is64;
    if (tid == 0) {
        const unsigned int* wp = (const unsigned int*)tgt_raw;
        int is64 = 1;
#pragma unroll
        for (int k = 0; k < 32; ++k)
            if (wp[2 * k + 1] != 0u) { is64 = 0; break; }
        s_is64 = is64;
    }
    __syncthreads();
    const int is64 = s_is64;
    const long long* t64 = (const long long*)tgt_raw;
    const int*       t32 = (const int*)tgt_raw;

    float local = 0.0f;
    int   mcnt  = 0;

    for (int t = tid; t < T_; t += 256) {
        const int mk = mask[t * B_ + b];
        mcnt += mk;
        if (t >= 1 && mk) {
            const int cur = is64 ? (int)t64[t * B_ + b]       : t32[t * B_ + b];
            const int prv = is64 ? (int)t64[(t - 1) * B_ + b] : t32[(t - 1) * B_ + b];
            local += trans[prv * L_ + cur] +
                     pred[(size_t)t * (B_ * L_) + b * L_ + cur];
        }
    }

    __shared__ float sf[8];
    __shared__ int   si[8];
#pragma unroll
    for (int off = 16; off; off >>= 1) {
        local += __shfl_xor_sync(0xffffffffu, local, off);
        mcnt  += __shfl_xor_sync(0xffffffffu, mcnt,  off);
    }
    if (lane == 0) { sf[wid] = local; si[wid] = mcnt; }
    __syncthreads();

    if (tid == 0) {
        float tot = 0.0f;
        int   mt  = 0;
#pragma unroll
        for (int q = 0; q < 8; ++q) { tot += sf[q]; mt += si[q]; }
        const int t0 = is64 ? (int)t64[b] : t32[b];
        float sc = start[t0] + pred[b * L_ + t0] + tot;
        const int last = mt - 1;
        const int tl = is64 ? (int)t64[last * B_ + b] : t32[last * B_ + b];
        sc += endv[tl];
        g_num[b] = sc;
    }
}

// ---------------------------------------------------------------------------
// Final: out = mean(den - num)
// ---------------------------------------------------------------------------
__global__ __launch_bounds__(B_) void crf_final_kernel(float* __restrict__ out)
{
    const int j    = threadIdx.x;
    const int lane = j & 31;
    const int wid  = j >> 5;

    float v = g_den[j] - g_num[j];
    __shared__ float red[4];
#pragma unroll
    for (int off = 16; off; off >>= 1)
        v += __shfl_xor_sync(0xffffffffu, v, off);
    if (lane == 0) red[wid] = v;
    __syncthreads();
    if (j == 0)
        out[0] = ((red[0] + red[1]) + (red[2] + red[3])) * (1.0f / (float)B_);
}

extern "C" void kernel_launch(void* const* d_in, const int* in_sizes, int n_in,
                              void* d_out, int out_size)
{
    const float* pred  = (const float*)d_in[0];
    const void*  tgt   = (const void*)d_in[1];
    const int*   mask  = (const int*)d_in[2];
    const float* trans = (const float*)d_in[3];
    const float* start = (const float*)d_in[4];
    const float* endv  = (const float*)d_in[5];
    float* out = (float*)d_out;

    crf_den_kernel<<<B_, 256>>>(pred, mask, trans, start, endv);
    crf_num_kernel<<<B_, 256>>>(pred, tgt, mask, trans, start, endv);
    crf_final_kernel<<<1, B_>>>(out);
}